// round 1
// baseline (speedup 1.0000x reference)
#include <cuda_runtime.h>
#include <math.h>

// ---------------------------------------------------------------------------
// SpatialTransformer: out = (x + softmax((xWq^T+bq)(ceWk^T+bk)^T/sqrt(C)) (ceWv^T+bv)) Wo^T + bo
// B=4, SQ=SKV=2048, C=1024. All fp32.
// Round 0: pure-fp32 SIMT tiled GEMMs (correctness anchor). Tensor cores later.
// ---------------------------------------------------------------------------

#define B_DIM 4
#define S_DIM 2048
#define C_DIM 1024
#define M_ALL (B_DIM * S_DIM)   // 8192

// Scratch (static device allocs are allowed; runtime allocs are not)
__device__ float g_Q[M_ALL * C_DIM];            // 32 MB
__device__ float g_K[M_ALL * C_DIM];            // 32 MB
__device__ float g_V[M_ALL * C_DIM];            // 32 MB
__device__ float g_S[(long long)B_DIM * S_DIM * S_DIM]; // 64 MB
__device__ float g_T[M_ALL * C_DIM];            // 32 MB (x + attended)

// ---------------------------------------------------------------------------
// Generic tiled GEMM: C = alpha * A @ op(B) [+ bias] [+ resid]
//   A: [M,K] row-major (per-batch stride sA)
//   TRANSB=1: B is [N,K] row-major (K contiguous)  -> C = A @ B^T
//   TRANSB=0: B is [K,N] row-major (N contiguous)  -> C = A @ B
//   C: [M,N] row-major (per-batch stride sC); resid uses same stride as C.
// Tiles: 128x128x8, 256 threads, 8x8 per-thread micro-tile, smem double-buffer.
// All of M,N divisible by 128 and K by 8 (true for every call site) -> no guards.
// ---------------------------------------------------------------------------
template<bool TRANSB, bool HAS_BIAS, bool HAS_RES>
__global__ __launch_bounds__(256)
void gemm_k(const float* __restrict__ A, const float* __restrict__ Bm,
            const float* __restrict__ bias, const float* __restrict__ Rm,
            float* __restrict__ Cm,
            int M, int N, int K, float alpha,
            long long sA, long long sB, long long sC)
{
    __shared__ float As[2][8][128];
    __shared__ float Bs[2][8][128];

    const int z = blockIdx.z;
    A  += z * sA;
    Bm += z * sB;
    Cm += z * sC;
    const float* Rp = HAS_RES ? (Rm + z * sC) : (const float*)nullptr;

    const int m0  = blockIdx.y * 128;
    const int n0  = blockIdx.x * 128;
    const int tid = threadIdx.x;
    const int tx  = tid & 15;        // 0..15 -> n
    const int ty  = tid >> 4;        // 0..15 -> m

    // A / B(NT) tile load mapping: 128 rows x 8 k, one float4 per thread
    const int lrow = tid >> 1;            // 0..127
    const int lk4  = (tid & 1) << 2;      // 0 or 4
    // B(NN) tile load mapping: 8 k-rows x 128 n, one float4 per thread
    const int bk   = tid >> 5;            // 0..7
    const int bn4  = (tid & 31) << 2;     // 0..124

    float acc[8][8];
#pragma unroll
    for (int i = 0; i < 8; i++)
#pragma unroll
        for (int j = 0; j < 8; j++) acc[i][j] = 0.f;

    const int nk = K >> 3;

    // preload tile 0
    {
        float4 ra = *reinterpret_cast<const float4*>(A + (long long)(m0 + lrow) * K + lk4);
        As[0][lk4 + 0][lrow] = ra.x; As[0][lk4 + 1][lrow] = ra.y;
        As[0][lk4 + 2][lrow] = ra.z; As[0][lk4 + 3][lrow] = ra.w;
        if (TRANSB) {
            float4 rb = *reinterpret_cast<const float4*>(Bm + (long long)(n0 + lrow) * K + lk4);
            Bs[0][lk4 + 0][lrow] = rb.x; Bs[0][lk4 + 1][lrow] = rb.y;
            Bs[0][lk4 + 2][lrow] = rb.z; Bs[0][lk4 + 3][lrow] = rb.w;
        } else {
            float4 rb = *reinterpret_cast<const float4*>(Bm + (long long)bk * N + n0 + bn4);
            *reinterpret_cast<float4*>(&Bs[0][bk][bn4]) = rb;
        }
    }
    __syncthreads();

    int cur = 0;
    for (int kt = 0; kt < nk; ++kt) {
        float4 na, nb;
        const bool more = (kt + 1 < nk);
        if (more) {
            const int k0 = (kt + 1) << 3;
            na = *reinterpret_cast<const float4*>(A + (long long)(m0 + lrow) * K + k0 + lk4);
            if (TRANSB)
                nb = *reinterpret_cast<const float4*>(Bm + (long long)(n0 + lrow) * K + k0 + lk4);
            else
                nb = *reinterpret_cast<const float4*>(Bm + (long long)(k0 + bk) * N + n0 + bn4);
        }

#pragma unroll
        for (int k = 0; k < 8; k++) {
            float4 a0 = *reinterpret_cast<const float4*>(&As[cur][k][ty * 8]);
            float4 a1 = *reinterpret_cast<const float4*>(&As[cur][k][ty * 8 + 4]);
            float4 b0 = *reinterpret_cast<const float4*>(&Bs[cur][k][tx * 8]);
            float4 b1 = *reinterpret_cast<const float4*>(&Bs[cur][k][tx * 8 + 4]);
            float a[8] = {a0.x, a0.y, a0.z, a0.w, a1.x, a1.y, a1.z, a1.w};
            float b[8] = {b0.x, b0.y, b0.z, b0.w, b1.x, b1.y, b1.z, b1.w};
#pragma unroll
            for (int i = 0; i < 8; i++)
#pragma unroll
                for (int j = 0; j < 8; j++)
                    acc[i][j] = fmaf(a[i], b[j], acc[i][j]);
        }

        if (more) {
            const int nxt = cur ^ 1;
            As[nxt][lk4 + 0][lrow] = na.x; As[nxt][lk4 + 1][lrow] = na.y;
            As[nxt][lk4 + 2][lrow] = na.z; As[nxt][lk4 + 3][lrow] = na.w;
            if (TRANSB) {
                Bs[nxt][lk4 + 0][lrow] = nb.x; Bs[nxt][lk4 + 1][lrow] = nb.y;
                Bs[nxt][lk4 + 2][lrow] = nb.z; Bs[nxt][lk4 + 3][lrow] = nb.w;
            } else {
                *reinterpret_cast<float4*>(&Bs[nxt][bk][bn4]) = nb;
            }
        }
        __syncthreads();
        cur ^= 1;
    }

    // epilogue
#pragma unroll
    for (int i = 0; i < 8; i++) {
        const int row = m0 + ty * 8 + i;
        const int col = n0 + tx * 8;
        float v[8];
#pragma unroll
        for (int j = 0; j < 8; j++) v[j] = acc[i][j] * alpha;
        if (HAS_BIAS) {
#pragma unroll
            for (int j = 0; j < 8; j++) v[j] += __ldg(&bias[col + j]);
        }
        if (HAS_RES) {
            float4 r0 = *reinterpret_cast<const float4*>(Rp + (long long)row * N + col);
            float4 r1 = *reinterpret_cast<const float4*>(Rp + (long long)row * N + col + 4);
            v[0] += r0.x; v[1] += r0.y; v[2] += r0.z; v[3] += r0.w;
            v[4] += r1.x; v[5] += r1.y; v[6] += r1.z; v[7] += r1.w;
        }
        float4 o0 = make_float4(v[0], v[1], v[2], v[3]);
        float4 o1 = make_float4(v[4], v[5], v[6], v[7]);
        *reinterpret_cast<float4*>(Cm + (long long)row * N + col)     = o0;
        *reinterpret_cast<float4*>(Cm + (long long)row * N + col + 4) = o1;
    }
}

// ---------------------------------------------------------------------------
// Row softmax, row length 2048, one block (256 threads) per row, values in regs.
// ---------------------------------------------------------------------------
__global__ __launch_bounds__(256)
void softmax2048(float* __restrict__ S)
{
    const long long row = blockIdx.x;
    float* p = S + row * 2048;
    const int tid = threadIdx.x;
    const int w = tid >> 5, l = tid & 31;

    float v[8];
    {
        float4 x0 = *reinterpret_cast<const float4*>(p + tid * 8);
        float4 x1 = *reinterpret_cast<const float4*>(p + tid * 8 + 4);
        v[0] = x0.x; v[1] = x0.y; v[2] = x0.z; v[3] = x0.w;
        v[4] = x1.x; v[5] = x1.y; v[6] = x1.z; v[7] = x1.w;
    }

    __shared__ float smax[8];
    __shared__ float ssum[8];

    float m = v[0];
#pragma unroll
    for (int j = 1; j < 8; j++) m = fmaxf(m, v[j]);
#pragma unroll
    for (int off = 16; off >= 1; off >>= 1)
        m = fmaxf(m, __shfl_xor_sync(0xffffffffu, m, off));
    if (l == 0) smax[w] = m;
    __syncthreads();
    float bm = smax[0];
#pragma unroll
    for (int j = 1; j < 8; j++) bm = fmaxf(bm, smax[j]);

    float s = 0.f;
#pragma unroll
    for (int j = 0; j < 8; j++) { v[j] = expf(v[j] - bm); s += v[j]; }
#pragma unroll
    for (int off = 16; off >= 1; off >>= 1)
        s += __shfl_xor_sync(0xffffffffu, s, off);
    if (l == 0) ssum[w] = s;
    __syncthreads();
    float tot = ssum[0];
#pragma unroll
    for (int j = 1; j < 8; j++) tot += ssum[j];

    const float inv = 1.f / tot;
#pragma unroll
    for (int j = 0; j < 8; j++) v[j] *= inv;

    float4 o0 = make_float4(v[0], v[1], v[2], v[3]);
    float4 o1 = make_float4(v[4], v[5], v[6], v[7]);
    *reinterpret_cast<float4*>(p + tid * 8)     = o0;
    *reinterpret_cast<float4*>(p + tid * 8 + 4) = o1;
}

// ---------------------------------------------------------------------------
extern "C" void kernel_launch(void* const* d_in, const int* in_sizes, int n_in,
                              void* d_out, int out_size)
{
    (void)in_sizes; (void)n_in; (void)out_size;
    const float* x  = (const float*)d_in[0];
    const float* ce = (const float*)d_in[1];
    const float* Wq = (const float*)d_in[2];
    const float* bq = (const float*)d_in[3];
    const float* Wk = (const float*)d_in[4];
    const float* bk = (const float*)d_in[5];
    const float* Wv = (const float*)d_in[6];
    const float* bv = (const float*)d_in[7];
    const float* Wo = (const float*)d_in[8];
    const float* bo = (const float*)d_in[9];
    float* out = (float*)d_out;

    float *Q, *K, *V, *S, *T;
    cudaGetSymbolAddress((void**)&Q, g_Q);
    cudaGetSymbolAddress((void**)&K, g_K);
    cudaGetSymbolAddress((void**)&V, g_V);
    cudaGetSymbolAddress((void**)&S, g_S);
    cudaGetSymbolAddress((void**)&T, g_T);

    const dim3 thr(256);
    const long long sQ  = (long long)S_DIM * C_DIM;   // 2048*1024
    const long long sS  = (long long)S_DIM * S_DIM;   // 2048*2048

    // Q/K/V projections: [8192,1024] = [8192,1024] @ [1024,1024]^T + b
    gemm_k<true, true, false><<<dim3(C_DIM / 128, M_ALL / 128, 1), thr>>>(
        x,  Wq, bq, nullptr, Q, M_ALL, C_DIM, C_DIM, 1.f, 0, 0, 0);
    gemm_k<true, true, false><<<dim3(C_DIM / 128, M_ALL / 128, 1), thr>>>(
        ce, Wk, bk, nullptr, K, M_ALL, C_DIM, C_DIM, 1.f, 0, 0, 0);
    gemm_k<true, true, false><<<dim3(C_DIM / 128, M_ALL / 128, 1), thr>>>(
        ce, Wv, bv, nullptr, V, M_ALL, C_DIM, C_DIM, 1.f, 0, 0, 0);

    // scores: per-batch [2048,2048] = Q @ K^T * (1/32)
    gemm_k<true, false, false><<<dim3(S_DIM / 128, S_DIM / 128, B_DIM), thr>>>(
        Q, K, nullptr, nullptr, S, S_DIM, S_DIM, C_DIM, 0.03125f, sQ, sQ, sS);

    // softmax over rows (B*SQ = 8192 rows of 2048)
    softmax2048<<<M_ALL, 256>>>(S);

    // attended + residual: T = P @ V + x  (per-batch [2048,1024], K=2048)
    gemm_k<false, false, true><<<dim3(C_DIM / 128, S_DIM / 128, B_DIM), thr>>>(
        S, V, nullptr, x, T, S_DIM, C_DIM, S_DIM, 1.f, sS, sQ, sQ);

    // output projection: out = T @ Wo^T + bo
    gemm_k<true, true, false><<<dim3(C_DIM / 128, M_ALL / 128, 1), thr>>>(
        T, Wo, bo, nullptr, out, M_ALL, C_DIM, C_DIM, 1.f, 0, 0, 0);
}

// round 3
// speedup vs baseline: 2.4079x; 2.4079x over previous
#include <cuda_runtime.h>
#include <cuda_bf16.h>
#include <cstdint>
#include <math.h>

// ---------------------------------------------------------------------------
// SpatialTransformer via mma.sync bf16 (HMMA) with hi/lo fp32 split.
// out = (x + softmax((xWq^T+bq)(ceWk^T+bk)^T/32)(ceWv^T+bv)) Wo^T + bo
// B=4, SQ=SKV=2048, C=1024, fp32 I/O.
// ---------------------------------------------------------------------------

#define B_DIM 4
#define S_DIM 2048
#define C_DIM 1024
#define M_ALL (B_DIM * S_DIM)   // 8192

__device__ float g_Q[M_ALL * C_DIM];
__device__ float g_K[M_ALL * C_DIM];
__device__ float g_Vt[C_DIM * M_ALL];                    // V^T: [C][B*S]
__device__ float g_S[(long long)B_DIM * S_DIM * S_DIM];
__device__ float g_T[M_ALL * C_DIM];

__device__ __forceinline__ uint32_t smem_u32(const void* p) {
    uint32_t a;
    asm("{ .reg .u64 t; cvta.to.shared.u64 t, %1; cvt.u32.u64 %0, t; }"
        : "=r"(a) : "l"(p));
    return a;
}

#define LDMX4(r0, r1, r2, r3, addr) \
    asm volatile("ldmatrix.sync.aligned.m8n8.x4.shared.b16 {%0,%1,%2,%3}, [%4];" \
                 : "=r"(r0), "=r"(r1), "=r"(r2), "=r"(r3) : "r"(addr))
#define LDMX2(r0, r1, addr) \
    asm volatile("ldmatrix.sync.aligned.m8n8.x2.shared.b16 {%0,%1}, [%2];" \
                 : "=r"(r0), "=r"(r1) : "r"(addr))
#define MMA16816(d, a, b) \
    asm volatile("mma.sync.aligned.m16n8k16.row.col.f32.bf16.bf16.f32 " \
                 "{%0,%1,%2,%3}, {%4,%5,%6,%7}, {%8,%9}, {%0,%1,%2,%3};" \
                 : "+f"((d)[0]), "+f"((d)[1]), "+f"((d)[2]), "+f"((d)[3]) \
                 : "r"((a)[0]), "r"((a)[1]), "r"((a)[2]), "r"((a)[3]), \
                   "r"((b)[0]), "r"((b)[1]))

// smem tile geometry: 128 rows x 32 k of bf16, padded row stride 40 halves
#define KT        32
#define ROW_H     40
#define TILE_H    (128 * ROW_H)          // halves per tile (5120)
#define STAGE_H   (4 * TILE_H)           // Ah, Al, Bh, Bl
#define SMEM_TOTAL (2 * STAGE_H * 2)     // bytes: 81920

__device__ __forceinline__ void split4(float4 v, uint2& hu, uint2& lu) {
    __nv_bfloat16 h0 = __float2bfloat16(v.x), h1 = __float2bfloat16(v.y);
    __nv_bfloat16 h2 = __float2bfloat16(v.z), h3 = __float2bfloat16(v.w);
    __nv_bfloat16 l0 = __float2bfloat16(v.x - __bfloat162float(h0));
    __nv_bfloat16 l1 = __float2bfloat16(v.y - __bfloat162float(h1));
    __nv_bfloat16 l2 = __float2bfloat16(v.z - __bfloat162float(h2));
    __nv_bfloat16 l3 = __float2bfloat16(v.w - __bfloat162float(h3));
    __nv_bfloat162 hp0, hp1, lp0, lp1;
    hp0.x = h0; hp0.y = h1; hp1.x = h2; hp1.y = h3;
    lp0.x = l0; lp0.y = l1; lp1.x = l2; lp1.y = l3;
    hu = make_uint2(*(uint32_t*)&hp0, *(uint32_t*)&hp1);
    lu = make_uint2(*(uint32_t*)&lp0, *(uint32_t*)&lp1);
}

// ---------------------------------------------------------------------------
// D[M,N] = alpha * A[M,K] @ B[N,K]^T (+bias[n]) (+R). 128x128 tile, 256 thr.
// STORE_TRANS: C[n*ldC + m] scatter (used to produce V^T).
// ---------------------------------------------------------------------------
template<bool HAS_BIAS, bool HAS_RES, bool STORE_TRANS>
__global__ __launch_bounds__(256, 1)
void gemm_mma(const float* __restrict__ A, const float* __restrict__ Bm,
              const float* __restrict__ bias, const float* __restrict__ Rm,
              float* __restrict__ Cm, int K, float alpha,
              int ldA, int ldB, int ldC,
              long long sA, long long sB, long long sC, long long sR)
{
    extern __shared__ __align__(16) char smem_raw[];
    __nv_bfloat16* sh = reinterpret_cast<__nv_bfloat16*>(smem_raw);
    const uint32_t sm_base = smem_u32(sh);

    const int tid  = threadIdx.x;
    const int wid  = tid >> 5;
    const int lane = tid & 31;
    const int z    = blockIdx.z;
    const int m0   = blockIdx.y * 128;
    const int n0   = blockIdx.x * 128;

    const float* Ag = A  + z * sA + (size_t)m0 * ldA;
    const float* Bg = Bm + z * sB + (size_t)n0 * ldB;

    const int warp_m = (wid & 1) * 64;    // 2 m-warps
    const int warp_n = (wid >> 1) * 32;   // 4 n-warps

    // gmem load mapping: row = tid>>1, k half = (tid&1)*16
    const int lrow  = tid >> 1;
    const int lkb   = (tid & 1) * 16;

    float acc[4][4][4];
#pragma unroll
    for (int i = 0; i < 4; i++)
#pragma unroll
        for (int j = 0; j < 4; j++)
#pragma unroll
            for (int c = 0; c < 4; c++) acc[i][j][c] = 0.f;

    const int NK = K >> 5;

    float4 av[4], bv[4];
    // preload ktile 0
#pragma unroll
    for (int c = 0; c < 4; c++) {
        av[c] = *reinterpret_cast<const float4*>(Ag + (size_t)lrow * ldA + lkb + c * 4);
        bv[c] = *reinterpret_cast<const float4*>(Bg + (size_t)lrow * ldB + lkb + c * 4);
    }
    {
        __nv_bfloat16* Ah = sh;                 __nv_bfloat16* Al = sh + TILE_H;
        __nv_bfloat16* Bh = sh + 2 * TILE_H;    __nv_bfloat16* Bl = sh + 3 * TILE_H;
#pragma unroll
        for (int c = 0; c < 4; c++) {
            uint2 hu, lu;
            const int off = lrow * ROW_H + lkb + c * 4;
            split4(av[c], hu, lu);
            *reinterpret_cast<uint2*>(Ah + off) = hu;
            *reinterpret_cast<uint2*>(Al + off) = lu;
            split4(bv[c], hu, lu);
            *reinterpret_cast<uint2*>(Bh + off) = hu;
            *reinterpret_cast<uint2*>(Bl + off) = lu;
        }
    }
    __syncthreads();

    for (int kt = 0; kt < NK; ++kt) {
        const int buf = kt & 1;
        const bool more = (kt + 1 < NK);
        if (more) {
            const float* Ak = Ag + (size_t)(kt + 1) * KT;
            const float* Bk = Bg + (size_t)(kt + 1) * KT;
#pragma unroll
            for (int c = 0; c < 4; c++) {
                av[c] = *reinterpret_cast<const float4*>(Ak + (size_t)lrow * ldA + lkb + c * 4);
                bv[c] = *reinterpret_cast<const float4*>(Bk + (size_t)lrow * ldB + lkb + c * 4);
            }
        }

        // compute on buf
        const uint32_t stg = sm_base + (uint32_t)(buf * STAGE_H) * 2;
#pragma unroll
        for (int kk = 0; kk < KT; kk += 16) {
            uint32_t aH[4][4], aL[4][4], bH[4][2], bL[4][2];
            const int arow = warp_m + (lane & 15);
            const int acol = kk + ((lane >> 4) << 3);
#pragma unroll
            for (int i = 0; i < 4; i++) {
                const uint32_t byt = (uint32_t)(((arow + i * 16) * ROW_H + acol) * 2);
                LDMX4(aH[i][0], aH[i][1], aH[i][2], aH[i][3], stg + byt);
                LDMX4(aL[i][0], aL[i][1], aL[i][2], aL[i][3], stg + (uint32_t)(TILE_H * 2) + byt);
            }
            const int brow = warp_n + (lane & 7);
            const int bcol = kk + (lane & 8);
#pragma unroll
            for (int j = 0; j < 4; j++) {
                const uint32_t byt = (uint32_t)(((brow + j * 8) * ROW_H + bcol) * 2);
                LDMX2(bH[j][0], bH[j][1], stg + (uint32_t)(2 * TILE_H * 2) + byt);
                LDMX2(bL[j][0], bL[j][1], stg + (uint32_t)(3 * TILE_H * 2) + byt);
            }
            // a-fragment order from x4: {r0,r1}=k0-7 rows lo/hi, {r2,r3}=k8-15
            // matches m16n8k16 A operand {a0,a1,a2,a3} directly.
#pragma unroll
            for (int i = 0; i < 4; i++)
#pragma unroll
                for (int j = 0; j < 4; j++) {
                    MMA16816(acc[i][j], aH[i], bH[j]);
                    MMA16816(acc[i][j], aH[i], bL[j]);
                    MMA16816(acc[i][j], aL[i], bH[j]);
                }
        }

        if (more) {
            const int nbuf = buf ^ 1;
            __nv_bfloat16* Ah = sh + nbuf * STAGE_H;
            __nv_bfloat16* Al = Ah + TILE_H;
            __nv_bfloat16* Bh = Al + TILE_H;
            __nv_bfloat16* Bl = Bh + TILE_H;
#pragma unroll
            for (int c = 0; c < 4; c++) {
                uint2 hu, lu;
                const int off = lrow * ROW_H + lkb + c * 4;
                split4(av[c], hu, lu);
                *reinterpret_cast<uint2*>(Ah + off) = hu;
                *reinterpret_cast<uint2*>(Al + off) = lu;
                split4(bv[c], hu, lu);
                *reinterpret_cast<uint2*>(Bh + off) = hu;
                *reinterpret_cast<uint2*>(Bl + off) = lu;
            }
        }
        __syncthreads();
    }

    // epilogue
    const int gq = lane >> 2;        // 0..7
    const int tq = lane & 3;         // 0..3
#pragma unroll
    for (int i = 0; i < 4; i++) {
#pragma unroll
        for (int j = 0; j < 4; j++) {
            const int col = n0 + warp_n + j * 8 + tq * 2;
#pragma unroll
            for (int h = 0; h < 2; h++) {   // h=0: row r0, h=1: row r0+8
                const int row = m0 + warp_m + i * 16 + gq + h * 8;
                float v0 = acc[i][j][2 * h]     * alpha;
                float v1 = acc[i][j][2 * h + 1] * alpha;
                if (HAS_BIAS) {
                    float2 bb = *reinterpret_cast<const float2*>(bias + col);
                    v0 += bb.x; v1 += bb.y;
                }
                if (STORE_TRANS) {
                    Cm[z * sC + (size_t)col * ldC + row]       = v0;
                    Cm[z * sC + (size_t)(col + 1) * ldC + row] = v1;
                } else {
                    float* op = Cm + z * sC + (size_t)row * ldC + col;
                    if (HAS_RES) {
                        float2 r = *reinterpret_cast<const float2*>(
                            Rm + z * sR + (size_t)row * ldC + col);
                        v0 += r.x; v1 += r.y;
                    }
                    *reinterpret_cast<float2*>(op) = make_float2(v0, v1);
                }
            }
        }
    }
}

// ---------------------------------------------------------------------------
__global__ __launch_bounds__(256)
void softmax2048(float* __restrict__ S)
{
    const long long row = blockIdx.x;
    float* p = S + row * 2048;
    const int tid = threadIdx.x;
    const int w = tid >> 5, l = tid & 31;

    float v[8];
    {
        float4 x0 = *reinterpret_cast<const float4*>(p + tid * 8);
        float4 x1 = *reinterpret_cast<const float4*>(p + tid * 8 + 4);
        v[0] = x0.x; v[1] = x0.y; v[2] = x0.z; v[3] = x0.w;
        v[4] = x1.x; v[5] = x1.y; v[6] = x1.z; v[7] = x1.w;
    }
    __shared__ float smax[8], ssum[8];

    float m = v[0];
#pragma unroll
    for (int j = 1; j < 8; j++) m = fmaxf(m, v[j]);
#pragma unroll
    for (int off = 16; off >= 1; off >>= 1)
        m = fmaxf(m, __shfl_xor_sync(0xffffffffu, m, off));
    if (l == 0) smax[w] = m;
    __syncthreads();
    float bm = smax[0];
#pragma unroll
    for (int j = 1; j < 8; j++) bm = fmaxf(bm, smax[j]);

    float s = 0.f;
#pragma unroll
    for (int j = 0; j < 8; j++) { v[j] = expf(v[j] - bm); s += v[j]; }
#pragma unroll
    for (int off = 16; off >= 1; off >>= 1)
        s += __shfl_xor_sync(0xffffffffu, s, off);
    if (l == 0) ssum[w] = s;
    __syncthreads();
    float tot = ssum[0];
#pragma unroll
    for (int j = 1; j < 8; j++) tot += ssum[j];

    const float inv = 1.f / tot;
#pragma unroll
    for (int j = 0; j < 8; j++) v[j] *= inv;
    *reinterpret_cast<float4*>(p + tid * 8)     = make_float4(v[0], v[1], v[2], v[3]);
    *reinterpret_cast<float4*>(p + tid * 8 + 4) = make_float4(v[4], v[5], v[6], v[7]);
}

// ---------------------------------------------------------------------------
extern "C" void kernel_launch(void* const* d_in, const int* in_sizes, int n_in,
                              void* d_out, int out_size)
{
    (void)in_sizes; (void)n_in; (void)out_size;
    const float* x  = (const float*)d_in[0];
    const float* ce = (const float*)d_in[1];
    const float* Wq = (const float*)d_in[2];
    const float* bq = (const float*)d_in[3];
    const float* Wk = (const float*)d_in[4];
    const float* bk = (const float*)d_in[5];
    const float* Wv = (const float*)d_in[6];
    const float* bv = (const float*)d_in[7];
    const float* Wo = (const float*)d_in[8];
    const float* bo = (const float*)d_in[9];
    float* out = (float*)d_out;

    float *Q, *K, *Vt, *S, *T;
    cudaGetSymbolAddress((void**)&Q,  g_Q);
    cudaGetSymbolAddress((void**)&K,  g_K);
    cudaGetSymbolAddress((void**)&Vt, g_Vt);
    cudaGetSymbolAddress((void**)&S,  g_S);
    cudaGetSymbolAddress((void**)&T,  g_T);

    cudaFuncSetAttribute(gemm_mma<true,  false, false>, cudaFuncAttributeMaxDynamicSharedMemorySize, SMEM_TOTAL);
    cudaFuncSetAttribute(gemm_mma<true,  false, true >, cudaFuncAttributeMaxDynamicSharedMemorySize, SMEM_TOTAL);
    cudaFuncSetAttribute(gemm_mma<false, false, false>, cudaFuncAttributeMaxDynamicSharedMemorySize, SMEM_TOTAL);
    cudaFuncSetAttribute(gemm_mma<false, true,  false>, cudaFuncAttributeMaxDynamicSharedMemorySize, SMEM_TOTAL);

    const long long sQ = (long long)S_DIM * C_DIM;
    const long long sS = (long long)S_DIM * S_DIM;

    // Q/K projections: [8192,1024] = in @ W^T + b
    gemm_mma<true, false, false><<<dim3(8, 64, 1), 256, SMEM_TOTAL>>>(
        x,  Wq, bq, nullptr, Q, C_DIM, 1.f, C_DIM, C_DIM, C_DIM, 0, 0, 0, 0);
    gemm_mma<true, false, false><<<dim3(8, 64, 1), 256, SMEM_TOTAL>>>(
        ce, Wk, bk, nullptr, K, C_DIM, 1.f, C_DIM, C_DIM, C_DIM, 0, 0, 0, 0);
    // V projection stored transposed: Vt[ch][b*2048+tok], ldC = M_ALL
    gemm_mma<true, false, true><<<dim3(8, 64, 1), 256, SMEM_TOTAL>>>(
        ce, Wv, bv, nullptr, Vt, C_DIM, 1.f, C_DIM, C_DIM, M_ALL, 0, 0, 0, 0);

    // scores: per-batch [2048,2048] = Q @ K^T / 32
    gemm_mma<false, false, false><<<dim3(16, 16, B_DIM), 256, SMEM_TOTAL>>>(
        Q, K, nullptr, nullptr, S, C_DIM, 0.03125f, C_DIM, C_DIM, S_DIM, sQ, sQ, sS, 0);

    softmax2048<<<M_ALL, 256>>>(S);

    // attended + residual: T = P @ Vt^T + x (k runs over tokens)
    gemm_mma<false, true, false><<<dim3(8, 16, B_DIM), 256, SMEM_TOTAL>>>(
        S, Vt, nullptr, x, T, S_DIM, 1.f, S_DIM, M_ALL, C_DIM, sS, S_DIM, sQ, sQ);

    // output projection
    gemm_mma<true, false, false><<<dim3(8, 64, 1), 256, SMEM_TOTAL>>>(
        T, Wo, bo, nullptr, out, C_DIM, 1.f, C_DIM, C_DIM, C_DIM, 0, 0, 0, 0);
}

// round 4
// speedup vs baseline: 2.6470x; 1.0993x over previous
#include <cuda_runtime.h>
#include <cuda_bf16.h>
#include <cstdint>
#include <math.h>

// ---------------------------------------------------------------------------
// SpatialTransformer via mma.sync bf16 (HMMA) with hi/lo fp32 split.
// Round 4: 2 CTAs/SM (reg-capped), A-frag register reuse, B ldmatrix x4.
// ---------------------------------------------------------------------------

#define B_DIM 4
#define S_DIM 2048
#define C_DIM 1024
#define M_ALL (B_DIM * S_DIM)   // 8192

__device__ float g_Q[M_ALL * C_DIM];
__device__ float g_K[M_ALL * C_DIM];
__device__ float g_Vt[C_DIM * M_ALL];                    // V^T: [C][B*S]
__device__ float g_S[(long long)B_DIM * S_DIM * S_DIM];
__device__ float g_T[M_ALL * C_DIM];

__device__ __forceinline__ uint32_t smem_u32(const void* p) {
    uint32_t a;
    asm("{ .reg .u64 t; cvta.to.shared.u64 t, %1; cvt.u32.u64 %0, t; }"
        : "=r"(a) : "l"(p));
    return a;
}

#define LDMX4(r0, r1, r2, r3, addr) \
    asm volatile("ldmatrix.sync.aligned.m8n8.x4.shared.b16 {%0,%1,%2,%3}, [%4];" \
                 : "=r"(r0), "=r"(r1), "=r"(r2), "=r"(r3) : "r"(addr))
#define MMA16816(d, a, b) \
    asm volatile("mma.sync.aligned.m16n8k16.row.col.f32.bf16.bf16.f32 " \
                 "{%0,%1,%2,%3}, {%4,%5,%6,%7}, {%8,%9}, {%0,%1,%2,%3};" \
                 : "+f"((d)[0]), "+f"((d)[1]), "+f"((d)[2]), "+f"((d)[3]) \
                 : "r"((a)[0]), "r"((a)[1]), "r"((a)[2]), "r"((a)[3]), \
                   "r"((b)[0]), "r"((b)[1]))

// smem tile geometry: 128 rows x 32 k of bf16, padded row stride 40 halves
#define KT        32
#define ROW_H     40
#define TILE_H    (128 * ROW_H)          // halves per tile (5120)
#define STAGE_H   (4 * TILE_H)           // Ah, Al, Bh, Bl
#define SMEM_TOTAL (2 * STAGE_H * 2)     // bytes: 81920

__device__ __forceinline__ void split4(float4 v, uint2& hu, uint2& lu) {
    __nv_bfloat16 h0 = __float2bfloat16(v.x), h1 = __float2bfloat16(v.y);
    __nv_bfloat16 h2 = __float2bfloat16(v.z), h3 = __float2bfloat16(v.w);
    __nv_bfloat16 l0 = __float2bfloat16(v.x - __bfloat162float(h0));
    __nv_bfloat16 l1 = __float2bfloat16(v.y - __bfloat162float(h1));
    __nv_bfloat16 l2 = __float2bfloat16(v.z - __bfloat162float(h2));
    __nv_bfloat16 l3 = __float2bfloat16(v.w - __bfloat162float(h3));
    __nv_bfloat162 hp0, hp1, lp0, lp1;
    hp0.x = h0; hp0.y = h1; hp1.x = h2; hp1.y = h3;
    lp0.x = l0; lp0.y = l1; lp1.x = l2; lp1.y = l3;
    hu = make_uint2(*(uint32_t*)&hp0, *(uint32_t*)&hp1);
    lu = make_uint2(*(uint32_t*)&lp0, *(uint32_t*)&lp1);
}

// ---------------------------------------------------------------------------
// D[M,N] = alpha * A[M,K] @ B[N,K]^T (+bias[n]) (+R). 128x128 tile, 256 thr.
// ---------------------------------------------------------------------------
template<bool HAS_BIAS, bool HAS_RES, bool STORE_TRANS>
__global__ __launch_bounds__(256, 2)
void gemm_mma(const float* __restrict__ A, const float* __restrict__ Bm,
              const float* __restrict__ bias, const float* __restrict__ Rm,
              float* __restrict__ Cm, int K, float alpha,
              int ldA, int ldB, int ldC,
              long long sA, long long sB, long long sC, long long sR)
{
    extern __shared__ __align__(16) char smem_raw[];
    __nv_bfloat16* sh = reinterpret_cast<__nv_bfloat16*>(smem_raw);
    const uint32_t sm_base = smem_u32(sh);

    const int tid  = threadIdx.x;
    const int wid  = tid >> 5;
    const int lane = tid & 31;
    const int z    = blockIdx.z;
    const int m0   = blockIdx.y * 128;
    const int n0   = blockIdx.x * 128;

    const float* Ag = A  + z * sA + (size_t)m0 * ldA;
    const float* Bg = Bm + z * sB + (size_t)n0 * ldB;

    const int warp_m = (wid & 1) * 64;    // 2 m-warps
    const int warp_n = (wid >> 1) * 32;   // 4 n-warps

    // gmem load mapping: row = tid>>1, k half = (tid&1)*16
    const int lrow  = tid >> 1;
    const int lkb   = (tid & 1) * 16;
    const int soff  = lrow * ROW_H + lkb;

    // ldmatrix address components (precompute per-thread)
    const int arow = warp_m + (lane & 15);
    const int acolr = (lane >> 4) << 3;                       // +0 / +8
    const int brow = warp_n + ((lane >> 4) << 3) + (lane & 7);
    const int bcolr = lane & 8;

    float acc[4][4][4];
#pragma unroll
    for (int i = 0; i < 4; i++)
#pragma unroll
        for (int j = 0; j < 4; j++)
#pragma unroll
            for (int c = 0; c < 4; c++) acc[i][j][c] = 0.f;

    const int NK = K >> 5;

    // ---- fill stage 0
    {
        __nv_bfloat16* Ah = sh;                 __nv_bfloat16* Al = sh + TILE_H;
        __nv_bfloat16* Bh = sh + 2 * TILE_H;    __nv_bfloat16* Bl = sh + 3 * TILE_H;
#pragma unroll
        for (int c = 0; c < 4; c++) {
            float4 v = *reinterpret_cast<const float4*>(Ag + (size_t)lrow * ldA + lkb + c * 4);
            uint2 hu, lu; split4(v, hu, lu);
            *reinterpret_cast<uint2*>(Ah + soff + c * 4) = hu;
            *reinterpret_cast<uint2*>(Al + soff + c * 4) = lu;
            v = *reinterpret_cast<const float4*>(Bg + (size_t)lrow * ldB + lkb + c * 4);
            split4(v, hu, lu);
            *reinterpret_cast<uint2*>(Bh + soff + c * 4) = hu;
            *reinterpret_cast<uint2*>(Bl + soff + c * 4) = lu;
        }
    }
    __syncthreads();

    for (int kt = 0; kt < NK; ++kt) {
        const int buf = kt & 1;
        const bool more = (kt + 1 < NK);
        const uint32_t stg = sm_base + (uint32_t)(buf * STAGE_H) * 2;
        __nv_bfloat16* nb = sh + (buf ^ 1) * STAGE_H;

        float4 pv[4];
        // prefetch A(kt+1)
        if (more) {
            const float* Ak = Ag + (size_t)(kt + 1) * KT;
#pragma unroll
            for (int c = 0; c < 4; c++)
                pv[c] = *reinterpret_cast<const float4*>(Ak + (size_t)lrow * ldA + lkb + c * 4);
        }

        // ---- compute both k16 halves; interleave prefetch stores/loads
#pragma unroll
        for (int half = 0; half < 2; ++half) {
            const int kk = half * 16;
            uint32_t af[4][4];      // reused: hi then lo
            uint32_t bh[4][2], bl[4][2];

            // A hi
#pragma unroll
            for (int i = 0; i < 4; i++) {
                const uint32_t byt = (uint32_t)(((arow + i * 16) * ROW_H + kk + acolr) * 2);
                LDMX4(af[i][0], af[i][1], af[i][2], af[i][3], stg + byt);
            }
            // B hi+lo, combined x4 over j pairs
#pragma unroll
            for (int jj = 0; jj < 4; jj += 2) {
                const uint32_t byt = (uint32_t)(((brow + jj * 8) * ROW_H + kk + bcolr) * 2);
                LDMX4(bh[jj][0], bh[jj][1], bh[jj + 1][0], bh[jj + 1][1],
                      stg + (uint32_t)(2 * TILE_H * 2) + byt);
                LDMX4(bl[jj][0], bl[jj][1], bl[jj + 1][0], bl[jj + 1][1],
                      stg + (uint32_t)(3 * TILE_H * 2) + byt);
            }
            // Ah*Bh, Ah*Bl
#pragma unroll
            for (int i = 0; i < 4; i++)
#pragma unroll
                for (int j = 0; j < 4; j++) {
                    MMA16816(acc[i][j], af[i], bh[j]);
                    MMA16816(acc[i][j], af[i], bl[j]);
                }
            // A lo into same regs
#pragma unroll
            for (int i = 0; i < 4; i++) {
                const uint32_t byt = (uint32_t)(((arow + i * 16) * ROW_H + kk + acolr) * 2);
                LDMX4(af[i][0], af[i][1], af[i][2], af[i][3],
                      stg + (uint32_t)(TILE_H * 2) + byt);
            }
#pragma unroll
            for (int i = 0; i < 4; i++)
#pragma unroll
                for (int j = 0; j < 4; j++)
                    MMA16816(acc[i][j], af[i], bh[j]);

            if (more) {
                if (half == 0) {
                    // store A prefetch to next buffer, then prefetch B
#pragma unroll
                    for (int c = 0; c < 4; c++) {
                        uint2 hu, lu; split4(pv[c], hu, lu);
                        *reinterpret_cast<uint2*>(nb + soff + c * 4) = hu;
                        *reinterpret_cast<uint2*>(nb + TILE_H + soff + c * 4) = lu;
                    }
                    const float* Bk = Bg + (size_t)(kt + 1) * KT;
#pragma unroll
                    for (int c = 0; c < 4; c++)
                        pv[c] = *reinterpret_cast<const float4*>(Bk + (size_t)lrow * ldB + lkb + c * 4);
                } else {
                    // store B prefetch to next buffer
#pragma unroll
                    for (int c = 0; c < 4; c++) {
                        uint2 hu, lu; split4(pv[c], hu, lu);
                        *reinterpret_cast<uint2*>(nb + 2 * TILE_H + soff + c * 4) = hu;
                        *reinterpret_cast<uint2*>(nb + 3 * TILE_H + soff + c * 4) = lu;
                    }
                }
            }
        }
        __syncthreads();
    }

    // epilogue
    const int gq = lane >> 2;        // 0..7
    const int tq = lane & 3;         // 0..3
#pragma unroll
    for (int i = 0; i < 4; i++) {
#pragma unroll
        for (int j = 0; j < 4; j++) {
            const int col = n0 + warp_n + j * 8 + tq * 2;
#pragma unroll
            for (int h = 0; h < 2; h++) {
                const int row = m0 + warp_m + i * 16 + gq + h * 8;
                float v0 = acc[i][j][2 * h]     * alpha;
                float v1 = acc[i][j][2 * h + 1] * alpha;
                if (HAS_BIAS) {
                    float2 bb = *reinterpret_cast<const float2*>(bias + col);
                    v0 += bb.x; v1 += bb.y;
                }
                if (STORE_TRANS) {
                    Cm[z * sC + (size_t)col * ldC + row]       = v0;
                    Cm[z * sC + (size_t)(col + 1) * ldC + row] = v1;
                } else {
                    float* op = Cm + z * sC + (size_t)row * ldC + col;
                    if (HAS_RES) {
                        float2 r = *reinterpret_cast<const float2*>(
                            Rm + z * sR + (size_t)row * ldC + col);
                        v0 += r.x; v1 += r.y;
                    }
                    *reinterpret_cast<float2*>(op) = make_float2(v0, v1);
                }
            }
        }
    }
}

// ---------------------------------------------------------------------------
__global__ __launch_bounds__(256)
void softmax2048(float* __restrict__ S)
{
    const long long row = blockIdx.x;
    float* p = S + row * 2048;
    const int tid = threadIdx.x;
    const int w = tid >> 5, l = tid & 31;

    float v[8];
    {
        float4 x0 = *reinterpret_cast<const float4*>(p + tid * 8);
        float4 x1 = *reinterpret_cast<const float4*>(p + tid * 8 + 4);
        v[0] = x0.x; v[1] = x0.y; v[2] = x0.z; v[3] = x0.w;
        v[4] = x1.x; v[5] = x1.y; v[6] = x1.z; v[7] = x1.w;
    }
    __shared__ float smax[8], ssum[8];

    float m = v[0];
#pragma unroll
    for (int j = 1; j < 8; j++) m = fmaxf(m, v[j]);
#pragma unroll
    for (int off = 16; off >= 1; off >>= 1)
        m = fmaxf(m, __shfl_xor_sync(0xffffffffu, m, off));
    if (l == 0) smax[w] = m;
    __syncthreads();
    float bm = smax[0];
#pragma unroll
    for (int j = 1; j < 8; j++) bm = fmaxf(bm, smax[j]);

    float s = 0.f;
#pragma unroll
    for (int j = 0; j < 8; j++) { v[j] = expf(v[j] - bm); s += v[j]; }
#pragma unroll
    for (int off = 16; off >= 1; off >>= 1)
        s += __shfl_xor_sync(0xffffffffu, s, off);
    if (l == 0) ssum[w] = s;
    __syncthreads();
    float tot = ssum[0];
#pragma unroll
    for (int j = 1; j < 8; j++) tot += ssum[j];

    const float inv = 1.f / tot;
#pragma unroll
    for (int j = 0; j < 8; j++) v[j] *= inv;
    *reinterpret_cast<float4*>(p + tid * 8)     = make_float4(v[0], v[1], v[2], v[3]);
    *reinterpret_cast<float4*>(p + tid * 8 + 4) = make_float4(v[4], v[5], v[6], v[7]);
}

// ---------------------------------------------------------------------------
extern "C" void kernel_launch(void* const* d_in, const int* in_sizes, int n_in,
                              void* d_out, int out_size)
{
    (void)in_sizes; (void)n_in; (void)out_size;
    const float* x  = (const float*)d_in[0];
    const float* ce = (const float*)d_in[1];
    const float* Wq = (const float*)d_in[2];
    const float* bq = (const float*)d_in[3];
    const float* Wk = (const float*)d_in[4];
    const float* bk = (const float*)d_in[5];
    const float* Wv = (const float*)d_in[6];
    const float* bv = (const float*)d_in[7];
    const float* Wo = (const float*)d_in[8];
    const float* bo = (const float*)d_in[9];
    float* out = (float*)d_out;

    float *Q, *K, *Vt, *S, *T;
    cudaGetSymbolAddress((void**)&Q,  g_Q);
    cudaGetSymbolAddress((void**)&K,  g_K);
    cudaGetSymbolAddress((void**)&Vt, g_Vt);
    cudaGetSymbolAddress((void**)&S,  g_S);
    cudaGetSymbolAddress((void**)&T,  g_T);

    cudaFuncSetAttribute(gemm_mma<true,  false, false>, cudaFuncAttributeMaxDynamicSharedMemorySize, SMEM_TOTAL);
    cudaFuncSetAttribute(gemm_mma<true,  false, true >, cudaFuncAttributeMaxDynamicSharedMemorySize, SMEM_TOTAL);
    cudaFuncSetAttribute(gemm_mma<false, false, false>, cudaFuncAttributeMaxDynamicSharedMemorySize, SMEM_TOTAL);
    cudaFuncSetAttribute(gemm_mma<false, true,  false>, cudaFuncAttributeMaxDynamicSharedMemorySize, SMEM_TOTAL);

    const long long sQ = (long long)S_DIM * C_DIM;
    const long long sS = (long long)S_DIM * S_DIM;

    // Q/K projections: [8192,1024] = in @ W^T + b
    gemm_mma<true, false, false><<<dim3(8, 64, 1), 256, SMEM_TOTAL>>>(
        x,  Wq, bq, nullptr, Q, C_DIM, 1.f, C_DIM, C_DIM, C_DIM, 0, 0, 0, 0);
    gemm_mma<true, false, false><<<dim3(8, 64, 1), 256, SMEM_TOTAL>>>(
        ce, Wk, bk, nullptr, K, C_DIM, 1.f, C_DIM, C_DIM, C_DIM, 0, 0, 0, 0);
    // V projection stored transposed: Vt[ch][b*2048+tok], ldC = M_ALL
    gemm_mma<true, false, true><<<dim3(8, 64, 1), 256, SMEM_TOTAL>>>(
        ce, Wv, bv, nullptr, Vt, C_DIM, 1.f, C_DIM, C_DIM, M_ALL, 0, 0, 0, 0);

    // scores: per-batch [2048,2048] = Q @ K^T / 32
    gemm_mma<false, false, false><<<dim3(16, 16, B_DIM), 256, SMEM_TOTAL>>>(
        Q, K, nullptr, nullptr, S, C_DIM, 0.03125f, C_DIM, C_DIM, S_DIM, sQ, sQ, sS, 0);

    softmax2048<<<M_ALL, 256>>>(S);

    // attended + residual: T = P @ Vt^T + x (k runs over tokens)
    gemm_mma<false, true, false><<<dim3(8, 16, B_DIM), 256, SMEM_TOTAL>>>(
        S, Vt, nullptr, x, T, S_DIM, 1.f, S_DIM, M_ALL, C_DIM, sS, S_DIM, sQ, sQ);

    // output projection
    gemm_mma<true, false, false><<<dim3(8, 64, 1), 256, SMEM_TOTAL>>>(
        T, Wo, bo, nullptr, out, C_DIM, 1.f, C_DIM, C_DIM, C_DIM, 0, 0, 0, 0);
}